// round 2
// baseline (speedup 1.0000x reference)
#include <cuda_runtime.h>
#include <cuda_bf16.h>
#include <math.h>

// Problem constants
#define BT   4096      // B*S tokens
#define DD   1024
#define HH   2048
#define OO   1024
#define EE   8
#define TOPK 2
#define NPAIR (BT*TOPK)   // 8192
#define OUT_TENSOR (BT*OO) // 4194304

// ---------------- scratch (device globals; no allocation allowed) ----------------
__device__ float d_h1[(size_t)NPAIR * HH];   // 64 MB
__device__ float d_h2[(size_t)NPAIR * HH];   // 64 MB
__device__ int   d_pair_token[NPAIR];
__device__ float d_pair_gate[NPAIR];
__device__ int   d_counts[EE];
__device__ int   d_offsets[EE];
__device__ int   d_cursor[EE];
__device__ float d_sum_probs[EE];
__device__ float d_sum_gates[EE];
__device__ int   d_top_idx[NPAIR];
__device__ float d_top_g[NPAIR];

// ---------------- init: zero output + accumulators ----------------
__global__ void init_kernel(float* __restrict__ out, int n) {
    int i = blockIdx.x * blockDim.x + threadIdx.x;
    int stride = gridDim.x * blockDim.x;
    for (; i < n; i += stride) out[i] = 0.0f;
    if (blockIdx.x == 0 && threadIdx.x < EE) {
        d_counts[threadIdx.x] = 0;
        d_sum_probs[threadIdx.x] = 0.0f;
        d_sum_gates[threadIdx.x] = 0.0f;
    }
}

// ---------------- gating: logits, softmax stats, top-2 ----------------
__global__ void gating_kernel(const float* __restrict__ x,
                              const float* __restrict__ Wg,
                              const float* __restrict__ bg) {
    int t = blockIdx.x;
    int tid = threadIdx.x;              // 128 threads
    float acc[EE];
#pragma unroll
    for (int e = 0; e < EE; e++) acc[e] = 0.0f;

    const float* xr = x + (size_t)t * DD;
    for (int d = tid; d < DD; d += 128) {
        float xv = xr[d];
        const float* w = Wg + (size_t)d * EE;
#pragma unroll
        for (int e = 0; e < EE; e++) acc[e] += xv * w[e];
    }
    // warp reduce
#pragma unroll
    for (int e = 0; e < EE; e++) {
#pragma unroll
        for (int off = 16; off > 0; off >>= 1)
            acc[e] += __shfl_down_sync(0xffffffffu, acc[e], off);
    }
    __shared__ float sred[4][EE];
    int warp = tid >> 5, lane = tid & 31;
    if (lane == 0) {
#pragma unroll
        for (int e = 0; e < EE; e++) sred[warp][e] = acc[e];
    }
    __syncthreads();
    if (tid == 0) {
        float logit[EE];
#pragma unroll
        for (int e = 0; e < EE; e++)
            logit[e] = sred[0][e] + sred[1][e] + sred[2][e] + sred[3][e] + bg[e];

        // full softmax for aux stats
        float m = logit[0];
#pragma unroll
        for (int e = 1; e < EE; e++) m = fmaxf(m, logit[e]);
        float p[EE], se = 0.0f;
#pragma unroll
        for (int e = 0; e < EE; e++) { p[e] = __expf(logit[e] - m); se += p[e]; }
        float inv = 1.0f / se;
#pragma unroll
        for (int e = 0; e < EE; e++) atomicAdd(&d_sum_probs[e], p[e] * inv);

        // top-2 (first max keeps lowest index on ties, matching jax top_k)
        int i0 = 0;
#pragma unroll
        for (int e = 1; e < EE; e++) if (logit[e] > logit[i0]) i0 = e;
        int i1 = (i0 == 0) ? 1 : 0;
#pragma unroll
        for (int e = 0; e < EE; e++)
            if (e != i0 && logit[e] > logit[i1]) i1 = e;

        float l0 = logit[i0], l1 = logit[i1];
        float mm = fmaxf(l0, l1);
        float e0 = __expf(l0 - mm), e1 = __expf(l1 - mm);
        float s2 = e0 + e1;
        float g0 = e0 / s2, g1 = e1 / s2;

        atomicAdd(&d_sum_gates[i0], g0);
        atomicAdd(&d_sum_gates[i1], g1);
        atomicAdd(&d_counts[i0], 1);
        atomicAdd(&d_counts[i1], 1);
        d_top_idx[t * 2 + 0] = i0;  d_top_g[t * 2 + 0] = g0;
        d_top_idx[t * 2 + 1] = i1;  d_top_g[t * 2 + 1] = g1;
    }
}

// ---------------- finalize: prefix offsets + aux-loss outputs ----------------
__global__ void finalize_kernel(float* __restrict__ out) {
    if (threadIdx.x == 0 && blockIdx.x == 0) {
        int off = 0;
        for (int e = 0; e < EE; e++) {
            d_offsets[e] = off;
            off += d_counts[e];
            d_cursor[e] = 0;
        }
        float lb = 0.0f, ent = 0.0f;
        const float invT = 1.0f / (float)BT;
        for (int e = 0; e < EE; e++) {
            float ap = d_sum_probs[e] * invT;
            float ac = d_sum_gates[e] * invT;
            lb += ap * ac;
            ent -= ap * logf(ap + 1e-8f);
            out[OUT_TENSOR + 1 + e] = ac;       // avg_expert_counts
        }
        out[OUT_TENSOR] = 0.01f * (float)EE * lb; // load_balance_loss
        out[OUT_TENSOR + 1 + EE] = ent;           // gate_entropy
    }
}

// ---------------- scatter: build expert-grouped token lists ----------------
__global__ void scatter_kernel() {
    int j = blockIdx.x * blockDim.x + threadIdx.x;
    if (j >= NPAIR) return;
    int t = j >> 1;
    int e = d_top_idx[j];
    int pos = d_offsets[e] + atomicAdd(&d_cursor[e], 1);
    d_pair_token[pos] = t;
    d_pair_gate[pos]  = d_top_g[j];
}

// ---------------- expert GEMMs (64x64x16 tile, 256 thr, 4x4 microtile) ----------------
// LAYER 1: A = gather(x)[cnt,1024],  W1[e][1024,2048] -> relu -> h1
// LAYER 2: A = h1[cnt,2048],         W2[e][2048,2048] -> relu -> h2
// LAYER 3: A = h2[cnt,2048],         W3[e][2048,1024] -> gate * (.+b3) atomicAdd out
template<int LAYER>
__global__ __launch_bounds__(256)
void expert_gemm(const float* __restrict__ x,
                 const float* __restrict__ W,
                 const float* __restrict__ bias,
                 float* __restrict__ out) {
    constexpr int Kd = (LAYER == 1) ? DD : HH;
    constexpr int Nd = (LAYER == 3) ? OO : HH;

    const int e   = blockIdx.z;
    const int cnt = d_counts[e];
    const int mt  = blockIdx.y;
    if (mt * 64 >= cnt) return;
    const int base = d_offsets[e];
    const int nt   = blockIdx.x;

    __shared__ float As[16 * 68];
    __shared__ float Bs[16 * 64];
    __shared__ const float* rowptr[64];
    __shared__ int   rowtok[64];
    __shared__ float rowg[64];

    const int tid = threadIdx.x;
    if (tid < 64) {
        int gr = mt * 64 + tid;
        bool v = gr < cnt;
        if (LAYER == 1) {
            int tok = v ? d_pair_token[base + gr] : 0;
            rowptr[tid] = v ? (x + (size_t)tok * DD) : nullptr;
        } else {
            const float* src = (LAYER == 2) ? d_h1 : d_h2;
            rowptr[tid] = v ? (src + (size_t)(base + gr) * HH) : nullptr;
        }
        if (LAYER == 3) {
            rowtok[tid] = v ? d_pair_token[base + gr] : -1;
            rowg[tid]   = v ? d_pair_gate[base + gr]  : 0.0f;
        }
    }
    __syncthreads();

    const float* Bm = W + (size_t)e * Kd * Nd + (size_t)nt * 64;

    const int arow = tid >> 2;          // 0..63
    const int akc  = (tid & 3) * 4;     // 0,4,8,12
    const int brow = tid >> 4;          // 0..15
    const int bcol = (tid & 15) * 4;    // 0..60
    const int ty   = tid >> 4;          // m-group 0..15
    const int tx   = tid & 15;          // n-group 0..15

    const float* rp = rowptr[arow];     // constant across k-loop

    float acc[4][4];
#pragma unroll
    for (int i = 0; i < 4; i++)
#pragma unroll
        for (int j = 0; j < 4; j++) acc[i][j] = 0.0f;

    for (int k0 = 0; k0 < Kd; k0 += 16) {
        float4 av = rp ? *(const float4*)(rp + k0 + akc) : make_float4(0.f, 0.f, 0.f, 0.f);
        As[(akc + 0) * 68 + arow] = av.x;
        As[(akc + 1) * 68 + arow] = av.y;
        As[(akc + 2) * 68 + arow] = av.z;
        As[(akc + 3) * 68 + arow] = av.w;
        float4 bv = *(const float4*)(Bm + (size_t)(k0 + brow) * Nd + bcol);
        *(float4*)&Bs[brow * 64 + bcol] = bv;
        __syncthreads();
#pragma unroll
        for (int kk = 0; kk < 16; kk++) {
            float4 a4 = *(const float4*)&As[kk * 68 + ty * 4];
            float4 b4 = *(const float4*)&Bs[kk * 64 + tx * 4];
            acc[0][0] += a4.x * b4.x; acc[0][1] += a4.x * b4.y; acc[0][2] += a4.x * b4.z; acc[0][3] += a4.x * b4.w;
            acc[1][0] += a4.y * b4.x; acc[1][1] += a4.y * b4.y; acc[1][2] += a4.y * b4.z; acc[1][3] += a4.y * b4.w;
            acc[2][0] += a4.z * b4.x; acc[2][1] += a4.z * b4.y; acc[2][2] += a4.z * b4.z; acc[2][3] += a4.z * b4.w;
            acc[3][0] += a4.w * b4.x; acc[3][1] += a4.w * b4.y; acc[3][2] += a4.w * b4.z; acc[3][3] += a4.w * b4.w;
        }
        __syncthreads();
    }

    // epilogue
    const float* brow_bias = bias + (size_t)e * Nd + nt * 64 + tx * 4;
#pragma unroll
    for (int i = 0; i < 4; i++) {
        int r  = ty * 4 + i;
        int gr = mt * 64 + r;
        if (gr >= cnt) continue;
        if (LAYER != 3) {
            float* dst = ((LAYER == 1) ? d_h1 : d_h2)
                         + (size_t)(base + gr) * HH + nt * 64 + tx * 4;
            float4 v;
            v.x = fmaxf(acc[i][0] + brow_bias[0], 0.0f);
            v.y = fmaxf(acc[i][1] + brow_bias[1], 0.0f);
            v.z = fmaxf(acc[i][2] + brow_bias[2], 0.0f);
            v.w = fmaxf(acc[i][3] + brow_bias[3], 0.0f);
            *(float4*)dst = v;
        } else {
            int tok = rowtok[r];
            float g = rowg[r];
            float* dst = out + (size_t)tok * OO + nt * 64 + tx * 4;
            atomicAdd(&dst[0], g * (acc[i][0] + brow_bias[0]));
            atomicAdd(&dst[1], g * (acc[i][1] + brow_bias[1]));
            atomicAdd(&dst[2], g * (acc[i][2] + brow_bias[2]));
            atomicAdd(&dst[3], g * (acc[i][3] + brow_bias[3]));
        }
    }
}

// ---------------- launch ----------------
extern "C" void kernel_launch(void* const* d_in, const int* in_sizes, int n_in,
                              void* d_out, int out_size) {
    const float* x  = (const float*)d_in[0];
    const float* Wg = (const float*)d_in[1];
    const float* bg = (const float*)d_in[2];
    const float* W1 = (const float*)d_in[3];
    const float* b1 = (const float*)d_in[4];
    const float* W2 = (const float*)d_in[5];
    const float* b2 = (const float*)d_in[6];
    const float* W3 = (const float*)d_in[7];
    const float* b3 = (const float*)d_in[8];
    float* out = (float*)d_out;

    init_kernel<<<2048, 256>>>(out, out_size);
    gating_kernel<<<BT, 128>>>(x, Wg, bg);
    finalize_kernel<<<1, 32>>>(out);
    scatter_kernel<<<NPAIR / 256, 256>>>();

    // max tokens per expert = BT (top-k indices are distinct per token) -> 64 m-tiles
    expert_gemm<1><<<dim3(HH / 64, 64, EE), 256>>>(x, W1, b1, out);
    expert_gemm<2><<<dim3(HH / 64, 64, EE), 256>>>(x, W2, b2, out);
    expert_gemm<3><<<dim3(OO / 64, 64, EE), 256>>>(x, W3, b3, out);
}

// round 6
// speedup vs baseline: 3.3087x; 3.3087x over previous
#include <cuda_runtime.h>
#include <cuda_bf16.h>
#include <math.h>
#include <stdint.h>

// Problem constants
#define BT   4096      // B*S tokens
#define DD   1024
#define HH   2048
#define OO   1024
#define EE   8
#define TOPK 2
#define NPAIR (BT*TOPK)    // 8192
#define OUT_TENSOR (BT*OO) // 4194304

// ================= small helpers =================
__device__ __forceinline__ uint32_t smem_to_u32(const void* p) {
    uint32_t a;
    asm("{ .reg .u64 t; cvta.to.shared.u64 t, %1; cvt.u32.u64 %0, t; }" : "=r"(a) : "l"(p));
    return a;
}
__device__ __forceinline__ float tf32r(float x) {
    uint32_t u;
    asm("cvt.rna.tf32.f32 %0, %1;" : "=r"(u) : "f"(x));
    return __uint_as_float(u);
}
#define CP_ASYNC16(dst, src) \
    asm volatile("cp.async.ca.shared.global [%0], [%1], 16;" :: "r"(dst), "l"(src))
#define CP_COMMIT() asm volatile("cp.async.commit_group;" ::: "memory")
#define CP_WAIT1()  asm volatile("cp.async.wait_group 1;" ::: "memory")
#define CP_WAIT0()  asm volatile("cp.async.wait_group 0;" ::: "memory")

__device__ __forceinline__ void mma_tf32(float& c0, float& c1, float& c2, float& c3,
                                         uint32_t a0, uint32_t a1, uint32_t a2, uint32_t a3,
                                         uint32_t b0, uint32_t b1) {
    asm volatile(
        "mma.sync.aligned.m16n8k8.row.col.f32.tf32.tf32.f32 "
        "{%0,%1,%2,%3}, {%4,%5,%6,%7}, {%8,%9}, {%0,%1,%2,%3};"
        : "+f"(c0), "+f"(c1), "+f"(c2), "+f"(c3)
        : "r"(a0), "r"(a1), "r"(a2), "r"(a3), "r"(b0), "r"(b1));
}

// ================= scratch =================
__device__ float d_h1[(size_t)NPAIR * HH];           // 64 MB
__device__ float d_h2[(size_t)NPAIR * HH];           // 64 MB
__device__ float d_xr[(size_t)BT * DD];              // 16 MB (tf32-rounded x)
__device__ float d_wt1[(size_t)EE * HH * DD];        // 64 MB  [E][H][D]
__device__ float d_wt2[(size_t)EE * HH * HH];        // 128 MB [E][H][H]
__device__ float d_wt3[(size_t)EE * OO * HH];        // 64 MB  [E][O][H]
__device__ int   d_pair_token[NPAIR];
__device__ float d_pair_gate[NPAIR];
__device__ int   d_counts[EE];
__device__ int   d_offsets[EE];
__device__ int   d_cursor[EE];
__device__ float d_sum_probs[EE];
__device__ float d_sum_gates[EE];
__device__ int   d_top_idx[NPAIR];
__device__ float d_top_g[NPAIR];

// ================= init =================
__global__ void init_kernel(float* __restrict__ out, int n) {
    int i = blockIdx.x * blockDim.x + threadIdx.x;
    int stride = gridDim.x * blockDim.x;
    for (; i < n; i += stride) out[i] = 0.0f;
    if (blockIdx.x == 0 && threadIdx.x < EE) {
        d_counts[threadIdx.x] = 0;
        d_sum_probs[threadIdx.x] = 0.0f;
        d_sum_gates[threadIdx.x] = 0.0f;
    }
}

// ================= round x to tf32 =================
__global__ void round_x_kernel(const float* __restrict__ x) {
    int i = blockIdx.x * blockDim.x + threadIdx.x;
    if (i < BT * DD) d_xr[i] = tf32r(x[i]);
}

// ================= weight transpose + tf32 round: W[e][R][C] -> Wt[e][C][R] =====
__global__ void transpose_kernel(const float* __restrict__ W, float* __restrict__ Wt,
                                 int R, int C) {
    __shared__ float t[32][33];
    const float* We = W + (size_t)blockIdx.z * R * C;
    float* Wte = Wt + (size_t)blockIdx.z * R * C;
    int c0 = blockIdx.x * 32, r0 = blockIdx.y * 32;
#pragma unroll
    for (int i = threadIdx.y; i < 32; i += 8)
        t[i][threadIdx.x] = tf32r(We[(size_t)(r0 + i) * C + c0 + threadIdx.x]);
    __syncthreads();
#pragma unroll
    for (int i = threadIdx.y; i < 32; i += 8)
        Wte[(size_t)(c0 + i) * R + r0 + threadIdx.x] = t[threadIdx.x][i];
}

// ================= gating =================
__global__ void gating_kernel(const float* __restrict__ x,
                              const float* __restrict__ Wg,
                              const float* __restrict__ bg) {
    int t = blockIdx.x;
    int tid = threadIdx.x;              // 128 threads
    float acc[EE];
#pragma unroll
    for (int e = 0; e < EE; e++) acc[e] = 0.0f;
    const float* xr = x + (size_t)t * DD;
    for (int d = tid; d < DD; d += 128) {
        float xv = xr[d];
        const float* w = Wg + (size_t)d * EE;
#pragma unroll
        for (int e = 0; e < EE; e++) acc[e] += xv * w[e];
    }
#pragma unroll
    for (int e = 0; e < EE; e++) {
#pragma unroll
        for (int off = 16; off > 0; off >>= 1)
            acc[e] += __shfl_down_sync(0xffffffffu, acc[e], off);
    }
    __shared__ float sred[4][EE];
    int warp = tid >> 5, lane = tid & 31;
    if (lane == 0) {
#pragma unroll
        for (int e = 0; e < EE; e++) sred[warp][e] = acc[e];
    }
    __syncthreads();
    if (tid == 0) {
        float logit[EE];
#pragma unroll
        for (int e = 0; e < EE; e++)
            logit[e] = sred[0][e] + sred[1][e] + sred[2][e] + sred[3][e] + bg[e];
        float m = logit[0];
#pragma unroll
        for (int e = 1; e < EE; e++) m = fmaxf(m, logit[e]);
        float p[EE], se = 0.0f;
#pragma unroll
        for (int e = 0; e < EE; e++) { p[e] = __expf(logit[e] - m); se += p[e]; }
        float inv = 1.0f / se;
#pragma unroll
        for (int e = 0; e < EE; e++) atomicAdd(&d_sum_probs[e], p[e] * inv);
        int i0 = 0;
#pragma unroll
        for (int e = 1; e < EE; e++) if (logit[e] > logit[i0]) i0 = e;
        int i1 = (i0 == 0) ? 1 : 0;
#pragma unroll
        for (int e = 0; e < EE; e++)
            if (e != i0 && logit[e] > logit[i1]) i1 = e;
        float l0 = logit[i0], l1 = logit[i1];
        float mm = fmaxf(l0, l1);
        float e0 = __expf(l0 - mm), e1 = __expf(l1 - mm);
        float s2 = e0 + e1;
        float g0 = e0 / s2, g1 = e1 / s2;
        atomicAdd(&d_sum_gates[i0], g0);
        atomicAdd(&d_sum_gates[i1], g1);
        atomicAdd(&d_counts[i0], 1);
        atomicAdd(&d_counts[i1], 1);
        d_top_idx[t * 2 + 0] = i0;  d_top_g[t * 2 + 0] = g0;
        d_top_idx[t * 2 + 1] = i1;  d_top_g[t * 2 + 1] = g1;
    }
}

// ================= finalize =================
__global__ void finalize_kernel(float* __restrict__ out) {
    if (threadIdx.x == 0 && blockIdx.x == 0) {
        int off = 0;
        for (int e = 0; e < EE; e++) {
            d_offsets[e] = off;
            off += d_counts[e];
            d_cursor[e] = 0;
        }
        float lb = 0.0f, ent = 0.0f;
        const float invT = 1.0f / (float)BT;
        for (int e = 0; e < EE; e++) {
            float ap = d_sum_probs[e] * invT;
            float ac = d_sum_gates[e] * invT;
            lb += ap * ac;
            ent -= ap * logf(ap + 1e-8f);
            out[OUT_TENSOR + 1 + e] = ac;
        }
        out[OUT_TENSOR] = 0.01f * (float)EE * lb;
        out[OUT_TENSOR + 1 + EE] = ent;
    }
}

// ================= scatter =================
__global__ void scatter_kernel() {
    int j = blockIdx.x * blockDim.x + threadIdx.x;
    if (j >= NPAIR) return;
    int t = j >> 1;
    int e = d_top_idx[j];
    int pos = d_offsets[e] + atomicAdd(&d_cursor[e], 1);
    d_pair_token[pos] = t;
    d_pair_gate[pos]  = d_top_g[j];
}

// ================= tf32 mma.sync expert GEMM =================
// CTA tile 128x128, K-stage 32, double-buffered cp.async, XOR-swizzled smem.
// warp grid 2(m) x 4(n); warp tile 64x32; mma m16n8k8.
// LAYER 1: A=gather(d_xr)[cnt,1024], Wt1[E][2048][1024] -> relu -> h1 (tf32-rounded)
// LAYER 2: A=h1[cnt,2048],           Wt2[E][2048][2048] -> relu -> h2 (tf32-rounded)
// LAYER 3: A=h2[cnt,2048],           Wt3[E][1024][2048] -> gate*(.+b3) atomicAdd out
#define KC 32
#define STAGE_BYTES 32768            // A 16KB + B 16KB
#define HDR_BYTES 1024
#define SMEM_DYN (HDR_BYTES + 2*STAGE_BYTES)

template<int LAYER>
__global__ __launch_bounds__(256)
void expert_gemm_mma(const float* __restrict__ Wt,
                     const float* __restrict__ bias,
                     float* __restrict__ out) {
    constexpr int Kd = (LAYER == 1) ? DD : HH;
    constexpr int Nd = (LAYER == 3) ? OO : HH;
    constexpr int NCH = Kd / KC;   // 32 or 64

    const int e   = blockIdx.z;
    const int cnt = d_counts[e];
    const int mtile = blockIdx.y;
    if (mtile * 128 >= cnt) return;
    const int base = d_offsets[e];
    const int nblk = blockIdx.x;

    extern __shared__ char smem_raw[];
    const uint32_t sb = smem_to_u32(smem_raw);
    int* stok   = (int*)smem_raw;            // [128]
    float* sgate = (float*)(smem_raw + 512); // [128]

    const int tid = threadIdx.x;
    const int wid = tid >> 5;
    const int lid = tid & 31;
    const int g   = lid >> 2;     // groupID 0..7
    const int tg  = lid & 3;      // thread-in-group 0..3
    const int m0  = (wid & 1) * 64;
    const int n0  = (wid >> 1) * 32;

    if (tid < 128) {
        int gr = mtile * 128 + tid;
        int idx = base + min(gr, cnt - 1);
        stok[tid]  = d_pair_token[idx];
        sgate[tid] = d_pair_gate[idx];
    }
    __syncthreads();

    // ---- loader mapping: 4 rows per thread for A and B, 16B per row-chunk ----
    const int lsub = tid & 7;     // float4-chunk col 0..7
    const int lrow = tid >> 3;    // 0..31
    const float* WtE = Wt + (size_t)e * Kd * Nd + (size_t)(nblk * 128) * Kd;
    const float* hsrc = (LAYER == 2) ? d_h1 : d_h2;

    uint32_t dstoff[4];
    const float* asrc[4];
    const float* bsrc[4];
#pragma unroll
    for (int i = 0; i < 4; i++) {
        int r = lrow + 32 * i;
        dstoff[i] = (uint32_t)((r * 32 + ((lsub ^ (r & 7)) << 2)) * 4);
        if (LAYER == 1) {
            asrc[i] = d_xr + (size_t)stok[r] * DD + lsub * 4;
        } else {
            int gr = min(mtile * 128 + r, cnt - 1);
            asrc[i] = hsrc + (size_t)(base + gr) * Kd + lsub * 4;
        }
        bsrc[i] = WtE + (size_t)r * Kd + lsub * 4;
    }

    float acc[4][4][4];
#pragma unroll
    for (int mt = 0; mt < 4; mt++)
#pragma unroll
        for (int nt = 0; nt < 4; nt++)
#pragma unroll
            for (int c = 0; c < 4; c++) acc[mt][nt][c] = 0.0f;

    // prologue: stage 0
    {
        uint32_t sa = sb + HDR_BYTES;
        uint32_t sbB = sa + 16384;
#pragma unroll
        for (int i = 0; i < 4; i++) CP_ASYNC16(sa + dstoff[i], asrc[i]);
#pragma unroll
        for (int i = 0; i < 4; i++) CP_ASYNC16(sbB + dstoff[i], bsrc[i]);
        CP_COMMIT();
    }

    for (int c = 0; c < NCH; c++) {
        if (c + 1 < NCH) {
            uint32_t sa = sb + HDR_BYTES + ((c + 1) & 1) * STAGE_BYTES;
            uint32_t sbB = sa + 16384;
            int k0 = (c + 1) * KC;
#pragma unroll
            for (int i = 0; i < 4; i++) CP_ASYNC16(sa + dstoff[i], asrc[i] + k0);
#pragma unroll
            for (int i = 0; i < 4; i++) CP_ASYNC16(sbB + dstoff[i], bsrc[i] + k0);
            CP_COMMIT();
            CP_WAIT1();
        } else {
            CP_WAIT0();
        }
        __syncthreads();

        const uint32_t* As = (const uint32_t*)(smem_raw + HDR_BYTES + (c & 1) * STAGE_BYTES);
        const uint32_t* Bs = As + 4096;

#pragma unroll
        for (int ks = 0; ks < 4; ks++) {
            const int x0 = ((ks * 2) ^ g) << 2;
            const int x1 = ((ks * 2 + 1) ^ g) << 2;
            uint32_t bfr[4][2];
#pragma unroll
            for (int nt = 0; nt < 4; nt++) {
                int bb = (n0 + nt * 8 + g) * 32 + tg;
                bfr[nt][0] = Bs[bb + x0];
                bfr[nt][1] = Bs[bb + x1];
            }
#pragma unroll
            for (int mt = 0; mt < 4; mt++) {
                int ab = (m0 + mt * 16 + g) * 32 + tg;
                uint32_t a0 = As[ab + x0];
                uint32_t a1 = As[ab + 256 + x0];
                uint32_t a2 = As[ab + x1];
                uint32_t a3 = As[ab + 256 + x1];
#pragma unroll
                for (int nt = 0; nt < 4; nt++)
                    mma_tf32(acc[mt][nt][0], acc[mt][nt][1], acc[mt][nt][2], acc[mt][nt][3],
                             a0, a1, a2, a3, bfr[nt][0], bfr[nt][1]);
            }
        }
        __syncthreads();
    }

    // ---- epilogue ----
    const float* biasE = bias + (size_t)e * Nd + nblk * 128;
    float* hdst = (LAYER == 1) ? d_h1 : d_h2;

#pragma unroll
    for (int mt = 0; mt < 4; mt++) {
#pragma unroll
        for (int nt = 0; nt < 4; nt++) {
            int col = n0 + nt * 8 + tg * 2;
            float bv0 = biasE[col], bv1 = biasE[col + 1];
#pragma unroll
            for (int half = 0; half < 2; half++) {
                int lr = m0 + mt * 16 + g + half * 8;
                int grow = mtile * 128 + lr;
                if (grow >= cnt) continue;
                float v0 = acc[mt][nt][half * 2 + 0] + bv0;
                float v1 = acc[mt][nt][half * 2 + 1] + bv1;
                if (LAYER != 3) {
                    float2 v;
                    v.x = tf32r(fmaxf(v0, 0.0f));
                    v.y = tf32r(fmaxf(v1, 0.0f));
                    *(float2*)(hdst + (size_t)(base + grow) * HH + nblk * 128 + col) = v;
                } else {
                    float gt = sgate[lr];
                    float* dst = out + (size_t)stok[lr] * OO + nblk * 128 + col;
                    atomicAdd(&dst[0], gt * v0);
                    atomicAdd(&dst[1], gt * v1);
                }
            }
        }
    }
}

// ================= launch =================
extern "C" void kernel_launch(void* const* d_in, const int* in_sizes, int n_in,
                              void* d_out, int out_size) {
    const float* x  = (const float*)d_in[0];
    const float* Wg = (const float*)d_in[1];
    const float* bg = (const float*)d_in[2];
    const float* W1 = (const float*)d_in[3];
    const float* b1 = (const float*)d_in[4];
    const float* W2 = (const float*)d_in[5];
    const float* b2 = (const float*)d_in[6];
    const float* W3 = (const float*)d_in[7];
    const float* b3 = (const float*)d_in[8];
    float* out = (float*)d_out;

    cudaFuncSetAttribute(expert_gemm_mma<1>, cudaFuncAttributeMaxDynamicSharedMemorySize, SMEM_DYN);
    cudaFuncSetAttribute(expert_gemm_mma<2>, cudaFuncAttributeMaxDynamicSharedMemorySize, SMEM_DYN);
    cudaFuncSetAttribute(expert_gemm_mma<3>, cudaFuncAttributeMaxDynamicSharedMemorySize, SMEM_DYN);

    float* wt1 = nullptr; cudaGetSymbolAddress((void**)&wt1, d_wt1);
    float* wt2 = nullptr; cudaGetSymbolAddress((void**)&wt2, d_wt2);
    float* wt3 = nullptr; cudaGetSymbolAddress((void**)&wt3, d_wt3);

    init_kernel<<<2048, 256>>>(out, out_size);
    round_x_kernel<<<(BT * DD) / 256, 256>>>(x);
    // weight transposes (+ tf32 rounding): W[e][R][C] -> Wt[e][C][R]
    transpose_kernel<<<dim3(HH/32, DD/32, EE), dim3(32,8)>>>(W1, wt1, DD, HH);
    transpose_kernel<<<dim3(HH/32, HH/32, EE), dim3(32,8)>>>(W2, wt2, HH, HH);
    transpose_kernel<<<dim3(OO/32, HH/32, EE), dim3(32,8)>>>(W3, wt3, HH, OO);

    gating_kernel<<<BT, 128>>>(x, Wg, bg);
    finalize_kernel<<<1, 32>>>(out);
    scatter_kernel<<<NPAIR / 256, 256>>>();

    expert_gemm_mma<1><<<dim3(HH/128, 32, EE), 256, SMEM_DYN>>>(wt1, b1, out);
    expert_gemm_mma<2><<<dim3(HH/128, 32, EE), 256, SMEM_DYN>>>(wt2, b2, out);
    expert_gemm_mma<3><<<dim3(OO/128, 32, EE), 256, SMEM_DYN>>>(wt3, b3, out);
}

// round 7
// speedup vs baseline: 3.7147x; 1.1227x over previous
#include <cuda_runtime.h>
#include <cuda_fp16.h>
#include <cuda_bf16.h>
#include <math.h>
#include <stdint.h>

// Problem constants
#define BT   4096      // B*S tokens
#define DD   1024
#define HH   2048
#define OO   1024
#define EE   8
#define TOPK 2
#define NPAIR (BT*TOPK)    // 8192
#define OUT_TENSOR (BT*OO) // 4194304

// ================= small helpers =================
__device__ __forceinline__ uint32_t smem_to_u32(const void* p) {
    uint32_t a;
    asm("{ .reg .u64 t; cvta.to.shared.u64 t, %1; cvt.u32.u64 %0, t; }" : "=r"(a) : "l"(p));
    return a;
}
#define CP_ASYNC16(dst, src) \
    asm volatile("cp.async.ca.shared.global [%0], [%1], 16;" :: "r"(dst), "l"(src))
#define CP_COMMIT() asm volatile("cp.async.commit_group;" ::: "memory")
#define CP_WAIT1()  asm volatile("cp.async.wait_group 1;" ::: "memory")
#define CP_WAIT0()  asm volatile("cp.async.wait_group 0;" ::: "memory")

__device__ __forceinline__ void mma_f16(float& c0, float& c1, float& c2, float& c3,
                                        uint32_t a0, uint32_t a1, uint32_t a2, uint32_t a3,
                                        uint32_t b0, uint32_t b1) {
    asm volatile(
        "mma.sync.aligned.m16n8k16.row.col.f32.f16.f16.f32 "
        "{%0,%1,%2,%3}, {%4,%5,%6,%7}, {%8,%9}, {%0,%1,%2,%3};"
        : "+f"(c0), "+f"(c1), "+f"(c2), "+f"(c3)
        : "r"(a0), "r"(a1), "r"(a2), "r"(a3), "r"(b0), "r"(b1));
}

// ================= scratch =================
__device__ __half d_h1[(size_t)NPAIR * HH];          // 32 MB
__device__ __half d_h2[(size_t)NPAIR * HH];          // 32 MB
__device__ __half d_xh[(size_t)BT * DD];             // 8 MB (fp16 x)
__device__ __half d_wt1[(size_t)EE * HH * DD];       // 32 MB  [E][H][D]
__device__ __half d_wt2[(size_t)EE * HH * HH];       // 64 MB  [E][H][H]
__device__ __half d_wt3[(size_t)EE * OO * HH];       // 32 MB  [E][O][H]
__device__ int   d_pair_token[NPAIR];
__device__ float d_pair_gate[NPAIR];
__device__ int   d_counts[EE];
__device__ int   d_offsets[EE];
__device__ int   d_cursor[EE];
__device__ float d_sum_probs[EE];
__device__ float d_sum_gates[EE];
__device__ int   d_top_idx[NPAIR];
__device__ float d_top_g[NPAIR];

// ================= init =================
__global__ void init_kernel(float* __restrict__ out, int n) {
    int i = blockIdx.x * blockDim.x + threadIdx.x;
    int stride = gridDim.x * blockDim.x;
    for (; i < n; i += stride) out[i] = 0.0f;
    if (blockIdx.x == 0 && threadIdx.x < EE) {
        d_counts[threadIdx.x] = 0;
        d_sum_probs[threadIdx.x] = 0.0f;
        d_sum_gates[threadIdx.x] = 0.0f;
    }
}

// ===== weight transpose + fp16 convert: W[e][R][C] -> Wt[e][C][R] (half) =====
__global__ void transpose_h_kernel(const float* __restrict__ W, __half* __restrict__ Wt,
                                   int R, int C) {
    __shared__ float t[32][33];
    const float* We = W + (size_t)blockIdx.z * R * C;
    __half* Wte = Wt + (size_t)blockIdx.z * R * C;
    int c0 = blockIdx.x * 32, r0 = blockIdx.y * 32;
    int tx = threadIdx.x, ty = threadIdx.y;
#pragma unroll
    for (int i = ty; i < 32; i += 8)
        t[i][tx] = We[(size_t)(r0 + i) * C + c0 + tx];
    __syncthreads();
    if (tx < 16) {
#pragma unroll
        for (int i = ty; i < 32; i += 8) {
            __half2 v = __floats2half2_rn(t[2 * tx][i], t[2 * tx + 1][i]);
            *(__half2*)(Wte + (size_t)(c0 + i) * R + r0 + 2 * tx) = v;
        }
    }
}

// ================= gating (also emits fp16 x) =================
__global__ void gating_kernel(const float* __restrict__ x,
                              const float* __restrict__ Wg,
                              const float* __restrict__ bg) {
    int t = blockIdx.x;
    int tid = threadIdx.x;              // 128 threads
    float acc[EE];
#pragma unroll
    for (int e = 0; e < EE; e++) acc[e] = 0.0f;
    const float* xr = x + (size_t)t * DD;
    __half* xh = d_xh + (size_t)t * DD;
    for (int d = tid; d < DD; d += 128) {
        float xv = xr[d];
        xh[d] = __float2half(xv);
        const float* w = Wg + (size_t)d * EE;
#pragma unroll
        for (int e = 0; e < EE; e++) acc[e] += xv * w[e];
    }
#pragma unroll
    for (int e = 0; e < EE; e++) {
#pragma unroll
        for (int off = 16; off > 0; off >>= 1)
            acc[e] += __shfl_down_sync(0xffffffffu, acc[e], off);
    }
    __shared__ float sred[4][EE];
    int warp = tid >> 5, lane = tid & 31;
    if (lane == 0) {
#pragma unroll
        for (int e = 0; e < EE; e++) sred[warp][e] = acc[e];
    }
    __syncthreads();
    if (tid == 0) {
        float logit[EE];
#pragma unroll
        for (int e = 0; e < EE; e++)
            logit[e] = sred[0][e] + sred[1][e] + sred[2][e] + sred[3][e] + bg[e];
        float m = logit[0];
#pragma unroll
        for (int e = 1; e < EE; e++) m = fmaxf(m, logit[e]);
        float p[EE], se = 0.0f;
#pragma unroll
        for (int e = 0; e < EE; e++) { p[e] = __expf(logit[e] - m); se += p[e]; }
        float inv = 1.0f / se;
#pragma unroll
        for (int e = 0; e < EE; e++) atomicAdd(&d_sum_probs[e], p[e] * inv);
        int i0 = 0;
#pragma unroll
        for (int e = 1; e < EE; e++) if (logit[e] > logit[i0]) i0 = e;
        int i1 = (i0 == 0) ? 1 : 0;
#pragma unroll
        for (int e = 0; e < EE; e++)
            if (e != i0 && logit[e] > logit[i1]) i1 = e;
        float l0 = logit[i0], l1 = logit[i1];
        float mm = fmaxf(l0, l1);
        float e0 = __expf(l0 - mm), e1 = __expf(l1 - mm);
        float s2 = e0 + e1;
        float g0 = e0 / s2, g1 = e1 / s2;
        atomicAdd(&d_sum_gates[i0], g0);
        atomicAdd(&d_sum_gates[i1], g1);
        atomicAdd(&d_counts[i0], 1);
        atomicAdd(&d_counts[i1], 1);
        d_top_idx[t * 2 + 0] = i0;  d_top_g[t * 2 + 0] = g0;
        d_top_idx[t * 2 + 1] = i1;  d_top_g[t * 2 + 1] = g1;
    }
}

// ================= finalize =================
__global__ void finalize_kernel(float* __restrict__ out) {
    if (threadIdx.x == 0 && blockIdx.x == 0) {
        int off = 0;
        for (int e = 0; e < EE; e++) {
            d_offsets[e] = off;
            off += d_counts[e];
            d_cursor[e] = 0;
        }
        float lb = 0.0f, ent = 0.0f;
        const float invT = 1.0f / (float)BT;
        for (int e = 0; e < EE; e++) {
            float ap = d_sum_probs[e] * invT;
            float ac = d_sum_gates[e] * invT;
            lb += ap * ac;
            ent -= ap * logf(ap + 1e-8f);
            out[OUT_TENSOR + 1 + e] = ac;
        }
        out[OUT_TENSOR] = 0.01f * (float)EE * lb;
        out[OUT_TENSOR + 1 + EE] = ent;
    }
}

// ================= scatter =================
__global__ void scatter_kernel() {
    int j = blockIdx.x * blockDim.x + threadIdx.x;
    if (j >= NPAIR) return;
    int t = j >> 1;
    int e = d_top_idx[j];
    int pos = d_offsets[e] + atomicAdd(&d_cursor[e], 1);
    d_pair_token[pos] = t;
    d_pair_gate[pos]  = d_top_g[j];
}

// ================= fp16 mma.sync expert GEMM =================
// CTA tile 128x128, K-stage 64 (fp16), double-buffered cp.async, XOR-swizzled smem.
// warp grid 2(m) x 4(n); warp tile 64x32; mma m16n8k16.f16 (fp32 accum).
// LAYER 1: A=gather(d_xh)[cnt,1024], Wt1[E][2048][1024] -> relu -> h1 (fp16)
// LAYER 2: A=h1[cnt,2048],           Wt2[E][2048][2048] -> relu -> h2 (fp16)
// LAYER 3: A=h2[cnt,2048],           Wt3[E][1024][2048] -> gate*(.+b3) atomicAdd out
#define KC 64
#define STAGE_BYTES 32768            // A 16KB + B 16KB
#define HDR_BYTES 1024
#define SMEM_DYN (HDR_BYTES + 2*STAGE_BYTES)

template<int LAYER>
__global__ __launch_bounds__(256, 2)
void expert_gemm_mma(const __half* __restrict__ Wt,
                     const float* __restrict__ bias,
                     float* __restrict__ out) {
    constexpr int Kd = (LAYER == 1) ? DD : HH;
    constexpr int Nd = (LAYER == 3) ? OO : HH;
    constexpr int NCH = Kd / KC;   // 16 or 32

    const int e   = blockIdx.z;
    const int cnt = d_counts[e];
    const int mtile = blockIdx.y;
    if (mtile * 128 >= cnt) return;
    const int base = d_offsets[e];
    const int nblk = blockIdx.x;

    extern __shared__ char smem_raw[];
    const uint32_t sb = smem_to_u32(smem_raw);
    int* stok    = (int*)smem_raw;            // [128]
    float* sgate = (float*)(smem_raw + 512);  // [128]

    const int tid = threadIdx.x;
    const int wid = tid >> 5;
    const int lid = tid & 31;
    const int g   = lid >> 2;     // groupID 0..7
    const int tg  = lid & 3;      // thread-in-group 0..3
    const int m0  = (wid & 1) * 64;
    const int n0  = (wid >> 1) * 32;

    if (tid < 128) {
        int gr = mtile * 128 + tid;
        int idx = base + min(gr, cnt - 1);
        stok[tid]  = d_pair_token[idx];
        sgate[tid] = d_pair_gate[idx];
    }
    __syncthreads();

    // ---- loader mapping: 4 rows/thread per matrix, 16B chunks, chunk^=(row&7) ----
    const int lsub = tid & 7;     // 16B-chunk col 0..7 (row = 64 halves = 128B)
    const int lrow = tid >> 3;    // 0..31
    const __half* WtE = Wt + (size_t)e * Kd * Nd + (size_t)(nblk * 128) * Kd;
    const __half* hsrc = (LAYER == 2) ? d_h1 : d_h2;

    uint32_t dstoff[4];
    const char* asrc[4];
    const char* bsrc[4];
#pragma unroll
    for (int i = 0; i < 4; i++) {
        int r = lrow + 32 * i;
        dstoff[i] = (uint32_t)(r * 128 + ((lsub ^ (r & 7)) << 4));
        if (LAYER == 1) {
            asrc[i] = (const char*)(d_xh + (size_t)stok[r] * DD) + lsub * 16;
        } else {
            int gr = min(mtile * 128 + r, cnt - 1);
            asrc[i] = (const char*)(hsrc + (size_t)(base + gr) * Kd) + lsub * 16;
        }
        bsrc[i] = (const char*)(WtE + (size_t)r * Kd) + lsub * 16;
    }

    float acc[4][4][4];
#pragma unroll
    for (int mt = 0; mt < 4; mt++)
#pragma unroll
        for (int nt = 0; nt < 4; nt++)
#pragma unroll
            for (int c = 0; c < 4; c++) acc[mt][nt][c] = 0.0f;

    // prologue: stage 0
    {
        uint32_t sa = sb + HDR_BYTES;
        uint32_t sbB = sa + 16384;
#pragma unroll
        for (int i = 0; i < 4; i++) CP_ASYNC16(sa + dstoff[i], asrc[i]);
#pragma unroll
        for (int i = 0; i < 4; i++) CP_ASYNC16(sbB + dstoff[i], bsrc[i]);
        CP_COMMIT();
    }

    for (int c = 0; c < NCH; c++) {
        if (c + 1 < NCH) {
            uint32_t sa = sb + HDR_BYTES + ((c + 1) & 1) * STAGE_BYTES;
            uint32_t sbB = sa + 16384;
            int kb = (c + 1) * KC * 2;   // bytes
#pragma unroll
            for (int i = 0; i < 4; i++) CP_ASYNC16(sa + dstoff[i], asrc[i] + kb);
#pragma unroll
            for (int i = 0; i < 4; i++) CP_ASYNC16(sbB + dstoff[i], bsrc[i] + kb);
            CP_COMMIT();
            CP_WAIT1();
        } else {
            CP_WAIT0();
        }
        __syncthreads();

        const uint32_t* As = (const uint32_t*)(smem_raw + HDR_BYTES + (c & 1) * STAGE_BYTES);
        const uint32_t* Bs = As + 4096;

#pragma unroll
        for (int ks = 0; ks < 4; ks++) {        // 4 k16-steps in KC=64
            const int x0 = ((ks * 2) ^ g) << 2;
            const int x1 = ((ks * 2 + 1) ^ g) << 2;
            uint32_t bfr[4][2];
#pragma unroll
            for (int nt = 0; nt < 4; nt++) {
                int bb = (n0 + nt * 8 + g) * 32 + tg;
                bfr[nt][0] = Bs[bb + x0];
                bfr[nt][1] = Bs[bb + x1];
            }
#pragma unroll
            for (int mt = 0; mt < 4; mt++) {
                int ab = (m0 + mt * 16 + g) * 32 + tg;
                uint32_t a0 = As[ab + x0];
                uint32_t a1 = As[ab + 256 + x0];
                uint32_t a2 = As[ab + x1];
                uint32_t a3 = As[ab + 256 + x1];
#pragma unroll
                for (int nt = 0; nt < 4; nt++)
                    mma_f16(acc[mt][nt][0], acc[mt][nt][1], acc[mt][nt][2], acc[mt][nt][3],
                            a0, a1, a2, a3, bfr[nt][0], bfr[nt][1]);
            }
        }
        __syncthreads();
    }

    // ---- epilogue ----
    const float* biasE = bias + (size_t)e * Nd + nblk * 128;
    __half* hdst = (LAYER == 1) ? d_h1 : d_h2;

#pragma unroll
    for (int mt = 0; mt < 4; mt++) {
#pragma unroll
        for (int nt = 0; nt < 4; nt++) {
            int col = n0 + nt * 8 + tg * 2;
            float bv0 = biasE[col], bv1 = biasE[col + 1];
#pragma unroll
            for (int half = 0; half < 2; half++) {
                int lr = m0 + mt * 16 + g + half * 8;
                int grow = mtile * 128 + lr;
                if (grow >= cnt) continue;
                float v0 = acc[mt][nt][half * 2 + 0] + bv0;
                float v1 = acc[mt][nt][half * 2 + 1] + bv1;
                if (LAYER != 3) {
                    __half2 v = __floats2half2_rn(fmaxf(v0, 0.0f), fmaxf(v1, 0.0f));
                    *(__half2*)(hdst + (size_t)(base + grow) * HH + nblk * 128 + col) = v;
                } else {
                    float gt = sgate[lr];
                    float* dst = out + (size_t)stok[lr] * OO + nblk * 128 + col;
                    atomicAdd(&dst[0], gt * v0);
                    atomicAdd(&dst[1], gt * v1);
                }
            }
        }
    }
}

// ================= launch =================
extern "C" void kernel_launch(void* const* d_in, const int* in_sizes, int n_in,
                              void* d_out, int out_size) {
    const float* x  = (const float*)d_in[0];
    const float* Wg = (const float*)d_in[1];
    const float* bg = (const float*)d_in[2];
    const float* W1 = (const float*)d_in[3];
    const float* b1 = (const float*)d_in[4];
    const float* W2 = (const float*)d_in[5];
    const float* b2 = (const float*)d_in[6];
    const float* W3 = (const float*)d_in[7];
    const float* b3 = (const float*)d_in[8];
    float* out = (float*)d_out;

    cudaFuncSetAttribute(expert_gemm_mma<1>, cudaFuncAttributeMaxDynamicSharedMemorySize, SMEM_DYN);
    cudaFuncSetAttribute(expert_gemm_mma<2>, cudaFuncAttributeMaxDynamicSharedMemorySize, SMEM_DYN);
    cudaFuncSetAttribute(expert_gemm_mma<3>, cudaFuncAttributeMaxDynamicSharedMemorySize, SMEM_DYN);

    __half* wt1 = nullptr; cudaGetSymbolAddress((void**)&wt1, d_wt1);
    __half* wt2 = nullptr; cudaGetSymbolAddress((void**)&wt2, d_wt2);
    __half* wt3 = nullptr; cudaGetSymbolAddress((void**)&wt3, d_wt3);

    init_kernel<<<2048, 256>>>(out, out_size);
    // weight transposes (+ fp16 convert): W[e][R][C] -> Wt[e][C][R]
    transpose_h_kernel<<<dim3(HH/32, DD/32, EE), dim3(32,8)>>>(W1, wt1, DD, HH);
    transpose_h_kernel<<<dim3(HH/32, HH/32, EE), dim3(32,8)>>>(W2, wt2, HH, HH);
    transpose_h_kernel<<<dim3(OO/32, HH/32, EE), dim3(32,8)>>>(W3, wt3, HH, OO);

    gating_kernel<<<BT, 128>>>(x, Wg, bg);
    finalize_kernel<<<1, 32>>>(out);
    scatter_kernel<<<NPAIR / 256, 256>>>();

    expert_gemm_mma<1><<<dim3(HH/128, 32, EE), 256, SMEM_DYN>>>(wt1, b1, out);
    expert_gemm_mma<2><<<dim3(HH/128, 32, EE), 256, SMEM_DYN>>>(wt2, b2, out);
    expert_gemm_mma<3><<<dim3(OO/128, 32, EE), 256, SMEM_DYN>>>(wt3, b3, out);
}

// round 8
// speedup vs baseline: 6.6375x; 1.7868x over previous
#include <cuda_runtime.h>
#include <cuda_fp16.h>
#include <cuda_bf16.h>
#include <math.h>
#include <stdint.h>

// Problem constants
#define BT   4096      // B*S tokens
#define DD   1024
#define HH   2048
#define OO   1024
#define EE   8
#define TOPK 2
#define NPAIR (BT*TOPK)    // 8192
#define OUT_TENSOR (BT*OO) // 4194304

// ================= small helpers =================
__device__ __forceinline__ uint32_t smem_to_u32(const void* p) {
    uint32_t a;
    asm("{ .reg .u64 t; cvta.to.shared.u64 t, %1; cvt.u32.u64 %0, t; }" : "=r"(a) : "l"(p));
    return a;
}
#define CP_ASYNC16(dst, src) \
    asm volatile("cp.async.ca.shared.global [%0], [%1], 16;" :: "r"(dst), "l"(src))
#define CP_COMMIT() asm volatile("cp.async.commit_group;" ::: "memory")
#define CP_WAIT1()  asm volatile("cp.async.wait_group 1;" ::: "memory")
#define CP_WAIT0()  asm volatile("cp.async.wait_group 0;" ::: "memory")

__device__ __forceinline__ void ldsm_x4(uint32_t& r0, uint32_t& r1, uint32_t& r2, uint32_t& r3,
                                        uint32_t addr) {
    asm volatile("ldmatrix.sync.aligned.m8n8.x4.shared.b16 {%0,%1,%2,%3}, [%4];"
                 : "=r"(r0), "=r"(r1), "=r"(r2), "=r"(r3) : "r"(addr));
}
__device__ __forceinline__ void ldsm_x4_t(uint32_t& r0, uint32_t& r1, uint32_t& r2, uint32_t& r3,
                                          uint32_t addr) {
    asm volatile("ldmatrix.sync.aligned.m8n8.x4.trans.shared.b16 {%0,%1,%2,%3}, [%4];"
                 : "=r"(r0), "=r"(r1), "=r"(r2), "=r"(r3) : "r"(addr));
}
__device__ __forceinline__ void mma_f16(float& c0, float& c1, float& c2, float& c3,
                                        uint32_t a0, uint32_t a1, uint32_t a2, uint32_t a3,
                                        uint32_t b0, uint32_t b1) {
    asm volatile(
        "mma.sync.aligned.m16n8k16.row.col.f32.f16.f16.f32 "
        "{%0,%1,%2,%3}, {%4,%5,%6,%7}, {%8,%9}, {%0,%1,%2,%3};"
        : "+f"(c0), "+f"(c1), "+f"(c2), "+f"(c3)
        : "r"(a0), "r"(a1), "r"(a2), "r"(a3), "r"(b0), "r"(b1));
}

// ================= scratch =================
__device__ __half d_h1[(size_t)NPAIR * HH];          // 32 MB
__device__ __half d_h2[(size_t)NPAIR * HH];          // 32 MB
__device__ __half d_xh[(size_t)BT * DD];             // 8 MB (fp16 x)
__device__ __half d_w1h[(size_t)EE * DD * HH];       // 32 MB  [E][D][H] (row-major K x N)
__device__ __half d_w2h[(size_t)EE * HH * HH];       // 64 MB  [E][H][H]
__device__ __half d_w3h[(size_t)EE * HH * OO];       // 32 MB  [E][H][O]
__device__ float  d_y[(size_t)NPAIR * OO];           // 32 MB gated partial outputs by position
__device__ int   d_pair_token[NPAIR];
__device__ float d_pair_gate[NPAIR];
__device__ int   d_pair_pos[NPAIR];                  // pair j -> position
__device__ int   d_counts[EE];
__device__ int   d_offsets[EE];
__device__ int   d_cursor[EE];
__device__ float d_sum_probs[EE];
__device__ float d_sum_gates[EE];
__device__ int   d_top_idx[NPAIR];
__device__ float d_top_g[NPAIR];

// ================= fused weight convert fp32 -> fp16 (no transpose needed) =====
#define N1 ((size_t)EE * DD * HH)   // 16,777,216
#define N2 ((size_t)EE * HH * HH)   // 33,554,432
#define N3 ((size_t)EE * HH * OO)   // 16,777,216
__global__ void convert_w_kernel(const float* __restrict__ W1,
                                 const float* __restrict__ W2,
                                 const float* __restrict__ W3) {
    size_t gid = (size_t)blockIdx.x * blockDim.x + threadIdx.x;
    size_t i8 = gid * 8;
    const float* src;
    __half* dst;
    size_t off;
    if (i8 < N1)            { src = W1; dst = d_w1h; off = i8; }
    else if (i8 < N1 + N2)  { src = W2; dst = d_w2h; off = i8 - N1; }
    else                    { src = W3; dst = d_w3h; off = i8 - N1 - N2; }
    float4 f0 = *(const float4*)(src + off);
    float4 f1 = *(const float4*)(src + off + 4);
    __half2 h[4];
    h[0] = __floats2half2_rn(f0.x, f0.y);
    h[1] = __floats2half2_rn(f0.z, f0.w);
    h[2] = __floats2half2_rn(f1.x, f1.y);
    h[3] = __floats2half2_rn(f1.z, f1.w);
    *(uint4*)(dst + off) = *(uint4*)h;
}

// ================= gating (also emits fp16 x, zero-inits accumulators via grid) =====
__global__ void gating_kernel(const float* __restrict__ x,
                              const float* __restrict__ Wg,
                              const float* __restrict__ bg) {
    int t = blockIdx.x;
    int tid = threadIdx.x;              // 128 threads
    if (t == 0 && tid < EE) { /* no-op: accumulators zeroed host-side order via init below */ }
    float acc[EE];
#pragma unroll
    for (int e = 0; e < EE; e++) acc[e] = 0.0f;
    const float* xr = x + (size_t)t * DD;
    __half* xh = d_xh + (size_t)t * DD;
    for (int d = tid; d < DD; d += 128) {
        float xv = xr[d];
        xh[d] = __float2half(xv);
        const float* w = Wg + (size_t)d * EE;
#pragma unroll
        for (int e = 0; e < EE; e++) acc[e] += xv * w[e];
    }
#pragma unroll
    for (int e = 0; e < EE; e++) {
#pragma unroll
        for (int off = 16; off > 0; off >>= 1)
            acc[e] += __shfl_down_sync(0xffffffffu, acc[e], off);
    }
    __shared__ float sred[4][EE];
    int warp = tid >> 5, lane = tid & 31;
    if (lane == 0) {
#pragma unroll
        for (int e = 0; e < EE; e++) sred[warp][e] = acc[e];
    }
    __syncthreads();
    if (tid == 0) {
        float logit[EE];
#pragma unroll
        for (int e = 0; e < EE; e++)
            logit[e] = sred[0][e] + sred[1][e] + sred[2][e] + sred[3][e] + bg[e];
        float m = logit[0];
#pragma unroll
        for (int e = 1; e < EE; e++) m = fmaxf(m, logit[e]);
        float p[EE], se = 0.0f;
#pragma unroll
        for (int e = 0; e < EE; e++) { p[e] = __expf(logit[e] - m); se += p[e]; }
        float inv = 1.0f / se;
#pragma unroll
        for (int e = 0; e < EE; e++) atomicAdd(&d_sum_probs[e], p[e] * inv);
        int i0 = 0;
#pragma unroll
        for (int e = 1; e < EE; e++) if (logit[e] > logit[i0]) i0 = e;
        int i1 = (i0 == 0) ? 1 : 0;
#pragma unroll
        for (int e = 0; e < EE; e++)
            if (e != i0 && logit[e] > logit[i1]) i1 = e;
        float l0 = logit[i0], l1 = logit[i1];
        float mm = fmaxf(l0, l1);
        float e0 = __expf(l0 - mm), e1 = __expf(l1 - mm);
        float s2 = e0 + e1;
        float g0 = e0 / s2, g1 = e1 / s2;
        atomicAdd(&d_sum_gates[i0], g0);
        atomicAdd(&d_sum_gates[i1], g1);
        atomicAdd(&d_counts[i0], 1);
        atomicAdd(&d_counts[i1], 1);
        d_top_idx[t * 2 + 0] = i0;  d_top_g[t * 2 + 0] = g0;
        d_top_idx[t * 2 + 1] = i1;  d_top_g[t * 2 + 1] = g1;
    }
}

// tiny init for accumulators (before gating)
__global__ void init_acc_kernel() {
    if (threadIdx.x < EE) {
        d_counts[threadIdx.x] = 0;
        d_sum_probs[threadIdx.x] = 0.0f;
        d_sum_gates[threadIdx.x] = 0.0f;
    }
}

// ================= finalize: offsets + aux stats + tail-zero =================
__global__ void finalize_kernel(float* __restrict__ out, int out_size) {
    if (threadIdx.x == 0 && blockIdx.x == 0) {
        int off = 0;
        for (int e = 0; e < EE; e++) {
            d_offsets[e] = off;
            off += d_counts[e];
            d_cursor[e] = 0;
        }
        for (int i = OUT_TENSOR; i < out_size; i++) out[i] = 0.0f;  // tail is tiny
        float lb = 0.0f, ent = 0.0f;
        const float invT = 1.0f / (float)BT;
        for (int e = 0; e < EE; e++) {
            float ap = d_sum_probs[e] * invT;
            float ac = d_sum_gates[e] * invT;
            lb += ap * ac;
            ent -= ap * logf(ap + 1e-8f);
            out[OUT_TENSOR + 1 + e] = ac;
        }
        out[OUT_TENSOR] = 0.01f * (float)EE * lb;
        out[OUT_TENSOR + 1 + EE] = ent;
    }
}

// ================= scatter =================
__global__ void scatter_kernel() {
    int j = blockIdx.x * blockDim.x + threadIdx.x;
    if (j >= NPAIR) return;
    int t = j >> 1;
    int e = d_top_idx[j];
    int pos = d_offsets[e] + atomicAdd(&d_cursor[e], 1);
    d_pair_token[pos] = t;
    d_pair_gate[pos]  = d_top_g[j];
    d_pair_pos[j] = pos;
}

// ================= fp16 mma.sync expert GEMM (ldmatrix + 3-stage cp.async) ========
// CTA 128(M)x128(N), KC=64. A smem: [128][64h] m-major; B smem: [64][128h] k-major.
// warp grid 2(m) x 4(n); warp tile 64x32; mma m16n8k16 f32-accum.
// A frags: ldmatrix.x4; B frags: ldmatrix.x4.trans (weights used in native [K][N]).
#define KC 64
#define STAGE_BYTES 32768            // A 16KB + B 16KB
#define HDR_BYTES 1024
#define NSTAGE 3
#define SMEM_DYN (HDR_BYTES + NSTAGE*STAGE_BYTES)

template<int LAYER>
__global__ __launch_bounds__(256, 2)
void expert_gemm_mma(const __half* __restrict__ Wh,
                     const float* __restrict__ bias) {
    constexpr int Kd = (LAYER == 1) ? DD : HH;
    constexpr int Nd = (LAYER == 3) ? OO : HH;
    constexpr int NCH = Kd / KC;   // 16 or 32

    const int e   = blockIdx.z;
    const int cnt = d_counts[e];
    const int mtile = blockIdx.y;
    if (mtile * 128 >= cnt) return;
    const int base = d_offsets[e];
    const int nblk = blockIdx.x;

    extern __shared__ char smem_raw[];
    const uint32_t sb = smem_to_u32(smem_raw);
    int* stok    = (int*)smem_raw;            // [128]
    float* sgate = (float*)(smem_raw + 512);  // [128]

    const int tid = threadIdx.x;
    const int wid = tid >> 5;
    const int lid = tid & 31;
    const int g   = lid >> 2;     // 0..7
    const int tg  = lid & 3;      // 0..3
    const int m0  = (wid & 1) * 64;
    const int n0  = (wid >> 1) * 32;

    if (tid < 128) {
        int gr = mtile * 128 + tid;
        int idx = base + min(gr, cnt - 1);
        stok[tid]  = d_pair_token[idx];
        sgate[tid] = d_pair_gate[idx];
    }
    __syncthreads();

    // ---- cp.async mappings ----
    // A tile: 128 rows x 128B; chunk swizzle: phys = c ^ (r&7), c in 0..7
    const int lsubA = tid & 7, lrowA = tid >> 3;
    // B tile: 64 rows x 256B; chunk swizzle: phys = c ^ (r&7), c in 0..15
    const int lsubB = tid & 15, lrowB = tid >> 4;

    const __half* WhE = Wh + (size_t)e * Kd * Nd + (size_t)(nblk * 128);
    const __half* hsrc = (LAYER == 2) ? d_h1 : d_h2;

    uint32_t dstoffA[4], dstoffB[4];
    const char* asrc[4];
    const char* bsrc[4];
#pragma unroll
    for (int i = 0; i < 4; i++) {
        int rA = lrowA + 32 * i;
        dstoffA[i] = (uint32_t)(rA * 128 + ((lsubA ^ (rA & 7)) << 4));
        if (LAYER == 1) {
            asrc[i] = (const char*)(d_xh + (size_t)stok[rA] * DD) + lsubA * 16;
        } else {
            int gr = min(mtile * 128 + rA, cnt - 1);
            asrc[i] = (const char*)(hsrc + (size_t)(base + gr) * Kd) + lsubA * 16;
        }
        int rB = lrowB + 16 * i;
        dstoffB[i] = (uint32_t)(rB * 256 + ((lsubB ^ (rB & 7)) << 4));
        bsrc[i] = (const char*)(WhE + (size_t)rB * Nd) + lsubB * 16;
    }
    const size_t bstep = (size_t)KC * Nd * sizeof(__half);  // per-stage B advance

    // ---- ldmatrix lane constants ----
    const int til = lid >> 3, rin = lid & 7;
    const int thi = til >> 1, tlo = til & 1;
    uint32_t rowbaseA[4];
#pragma unroll
    for (int mt = 0; mt < 4; mt++)
        rowbaseA[mt] = (uint32_t)((m0 + mt * 16 + rin + tlo * 8) * 128);
    uint32_t koffA[4];
#pragma unroll
    for (int ks = 0; ks < 4; ks++)
        koffA[ks] = (uint32_t)((((ks * 2) + thi) ^ rin) << 4);
    const int klane = rin + tlo * 8;   // 0..15
    uint32_t lbB[2];
#pragma unroll
    for (int pr = 0; pr < 2; pr++) {
        int nc = (n0 >> 3) + pr * 2 + thi;
        lbB[pr] = (uint32_t)(klane * 256 + ((nc ^ (klane & 7)) << 4));
    }

    float acc[4][4][4];
#pragma unroll
    for (int mt = 0; mt < 4; mt++)
#pragma unroll
        for (int nt = 0; nt < 4; nt++)
#pragma unroll
            for (int c = 0; c < 4; c++) acc[mt][nt][c] = 0.0f;

    // ---- issue helper ----
    auto issue = [&](int s) {
        uint32_t sa = sb + HDR_BYTES + (s % NSTAGE) * STAGE_BYTES;
        uint32_t sB = sa + 16384;
        size_t aoff = (size_t)s * 128;       // 64 halves = 128 bytes along K
        size_t boff = (size_t)s * bstep;
#pragma unroll
        for (int i = 0; i < 4; i++) CP_ASYNC16(sa + dstoffA[i], asrc[i] + aoff);
#pragma unroll
        for (int i = 0; i < 4; i++) CP_ASYNC16(sB + dstoffB[i], bsrc[i] + boff);
    };

    issue(0); CP_COMMIT();
    issue(1); CP_COMMIT();

    for (int c = 0; c < NCH; c++) {
        if (c + 1 < NCH) { CP_WAIT1(); } else { CP_WAIT0(); }
        __syncthreads();
        if (c + 2 < NCH) { issue(c + 2); CP_COMMIT(); }

        uint32_t sa = sb + HDR_BYTES + (c % NSTAGE) * STAGE_BYTES;
        uint32_t sB = sa + 16384;
#pragma unroll
        for (int ks = 0; ks < 4; ks++) {
            uint32_t b[8];
            ldsm_x4_t(b[0], b[1], b[2], b[3], sB + lbB[0] + ks * 4096);
            ldsm_x4_t(b[4], b[5], b[6], b[7], sB + lbB[1] + ks * 4096);
#pragma unroll
            for (int mt = 0; mt < 4; mt++) {
                uint32_t a0, a1, a2, a3;
                ldsm_x4(a0, a1, a2, a3, sa + rowbaseA[mt] + koffA[ks]);
                mma_f16(acc[mt][0][0], acc[mt][0][1], acc[mt][0][2], acc[mt][0][3],
                        a0, a1, a2, a3, b[0], b[1]);
                mma_f16(acc[mt][1][0], acc[mt][1][1], acc[mt][1][2], acc[mt][1][3],
                        a0, a1, a2, a3, b[2], b[3]);
                mma_f16(acc[mt][2][0], acc[mt][2][1], acc[mt][2][2], acc[mt][2][3],
                        a0, a1, a2, a3, b[4], b[5]);
                mma_f16(acc[mt][3][0], acc[mt][3][1], acc[mt][3][2], acc[mt][3][3],
                        a0, a1, a2, a3, b[6], b[7]);
            }
        }
    }

    // ---- epilogue ----
    const float* biasE = bias + (size_t)e * Nd + nblk * 128;
    __half* hdst = (LAYER == 1) ? d_h1 : d_h2;

#pragma unroll
    for (int mt = 0; mt < 4; mt++) {
#pragma unroll
        for (int nt = 0; nt < 4; nt++) {
            int col = n0 + nt * 8 + tg * 2;
            float bv0 = biasE[col], bv1 = biasE[col + 1];
#pragma unroll
            for (int half = 0; half < 2; half++) {
                int lr = m0 + mt * 16 + g + half * 8;
                int grow = mtile * 128 + lr;
                if (grow >= cnt) continue;
                float v0 = acc[mt][nt][half * 2 + 0] + bv0;
                float v1 = acc[mt][nt][half * 2 + 1] + bv1;
                if (LAYER != 3) {
                    __half2 v = __floats2half2_rn(fmaxf(v0, 0.0f), fmaxf(v1, 0.0f));
                    *(__half2*)(hdst + (size_t)(base + grow) * HH + nblk * 128 + col) = v;
                } else {
                    float gt = sgate[lr];
                    float2 v = make_float2(gt * v0, gt * v1);
                    *(float2*)(d_y + (size_t)(base + grow) * OO + nblk * 128 + col) = v;
                }
            }
        }
    }
}

// ================= combine: out[t] = y[pos(2t)] + y[pos(2t+1)] =================
__global__ void combine_kernel(float* __restrict__ out) {
    int t = blockIdx.x;
    int p0 = d_pair_pos[2 * t];
    int p1 = d_pair_pos[2 * t + 1];
    const float4* y0 = (const float4*)(d_y + (size_t)p0 * OO);
    const float4* y1 = (const float4*)(d_y + (size_t)p1 * OO);
    float4* dst = (float4*)(out + (size_t)t * OO);
    int i = threadIdx.x;             // 256 threads, 256 float4 per row
    float4 a = y0[i], b = y1[i];
    dst[i] = make_float4(a.x + b.x, a.y + b.y, a.z + b.z, a.w + b.w);
}

// ================= launch =================
extern "C" void kernel_launch(void* const* d_in, const int* in_sizes, int n_in,
                              void* d_out, int out_size) {
    const float* x  = (const float*)d_in[0];
    const float* Wg = (const float*)d_in[1];
    const float* bg = (const float*)d_in[2];
    const float* W1 = (const float*)d_in[3];
    const float* b1 = (const float*)d_in[4];
    const float* W2 = (const float*)d_in[5];
    const float* b2 = (const float*)d_in[6];
    const float* W3 = (const float*)d_in[7];
    const float* b3 = (const float*)d_in[8];
    float* out = (float*)d_out;

    cudaFuncSetAttribute(expert_gemm_mma<1>, cudaFuncAttributeMaxDynamicSharedMemorySize, SMEM_DYN);
    cudaFuncSetAttribute(expert_gemm_mma<2>, cudaFuncAttributeMaxDynamicSharedMemorySize, SMEM_DYN);
    cudaFuncSetAttribute(expert_gemm_mma<3>, cudaFuncAttributeMaxDynamicSharedMemorySize, SMEM_DYN);

    __half* w1h = nullptr; cudaGetSymbolAddress((void**)&w1h, d_w1h);
    __half* w2h = nullptr; cudaGetSymbolAddress((void**)&w2h, d_w2h);
    __half* w3h = nullptr; cudaGetSymbolAddress((void**)&w3h, d_w3h);

    init_acc_kernel<<<1, 32>>>();
    convert_w_kernel<<<(unsigned)((N1 + N2 + N3) / 8 / 256), 256>>>(W1, W2, W3);
    gating_kernel<<<BT, 128>>>(x, Wg, bg);
    finalize_kernel<<<1, 32>>>(out, out_size);
    scatter_kernel<<<NPAIR / 256, 256>>>();
    expert_gemm_mma<1><<<dim3(HH/128, 32, EE), 256, SMEM_DYN>>>(w1h, b1);   // launch #6 -> ncu
    expert_gemm_mma<2><<<dim3(HH/128, 32, EE), 256, SMEM_DYN>>>(w2h, b2);
    expert_gemm_mma<3><<<dim3(OO/128, 32, EE), 256, SMEM_DYN>>>(w3h, b3);
    combine_kernel<<<BT, 256>>>(out);
}